// round 13
// baseline (speedup 1.0000x reference)
#include <cuda_runtime.h>
#include <cstdint>

typedef unsigned long long u64;
typedef unsigned int u32;
#define FULL 0xFFFFFFFFu

__device__ __forceinline__ float ex2(float x){
    float r; asm("ex2.approx.f32 %0,%1;" : "=f"(r) : "f"(x)); return r;
}
__device__ __forceinline__ float frcp(float x){
    float r; asm("rcp.approx.f32 %0,%1;" : "=f"(r) : "f"(x)); return r;
}
__device__ __forceinline__ u32 totf32(float x){
    u32 r; asm("cvt.rna.tf32.f32 %0,%1;" : "=r"(r) : "f"(x)); return r;
}
__device__ __forceinline__ void cpa16(u32 dst, const void* src){
    asm volatile("cp.async.cg.shared.global [%0], [%1], 16;" :: "r"(dst), "l"(src));
}
__device__ __forceinline__ void cp_commit(){ asm volatile("cp.async.commit_group;"); }
__device__ __forceinline__ void cp_wait1(){ asm volatile("cp.async.wait_group 1;"); }
__device__ __forceinline__ void cp_wait0(){ asm volatile("cp.async.wait_group 0;"); }

// per-CTA partials: [bh*4 + q4]
__device__ float g_Mp[512 * 4096];
__device__ float g_Sp[512 * 64];

__device__ __forceinline__ float get_cT(const float* __restrict__ delta){
    float d = delta[0];
    float t = (d > 20.f) ? d : log1pf(expf(d));
    return 1.44269504088896f / t;
}

#define MMA_TF32(C, a0,a1,a2,a3, b0,b1) \
    asm("mma.sync.aligned.m16n8k8.row.col.f32.tf32.tf32.f32 " \
        "{%0,%1,%2,%3},{%4,%5,%6,%7},{%8,%9},{%0,%1,%2,%3};" \
        : "+f"((C)[0]),"+f"((C)[1]),"+f"((C)[2]),"+f"((C)[3]) \
        : "r"(a0),"r"(a1),"r"(a2),"r"(a3), "r"(b0),"r"(b1))

// =====================================================================
// kv_mma: unchanged from round 12 (measured ~72us).
// =====================================================================
__global__ __launch_bounds__(128, 4) void kv_mma(
    const float* __restrict__ Kp, const float* __restrict__ Vp,
    const float* __restrict__ delta)
{
    __shared__ float pool[6912];   // k: 3x1152 at 0, v: 3x1152 at 3456

    const int bx   = blockIdx.x;
    const int bh   = bx >> 2;
    const int b    = bh >> 4, h = bh & 15;
    const int tid  = threadIdx.x;
    const int w    = tid >> 5, lane = tid & 31;
    const int g    = lane >> 2, tig = lane & 3;

    const float cT = get_cT(delta);
    const long cbase = ((long)b * 4096L) * 1024L + h * 64L;
    const float* kglob = Kp + cbase;
    const float* vglob = Vp + cbase;
    const long Lbase = (long)(bx & 3) * 1024;

    const u32 sb = (u32)__cvta_generic_to_shared(pool);

    for (int idx = tid; idx < 384; idx += 128){
        int bf3 = idx >> 7, rem = idx & 127;
        int row = rem >> 3, col = 64 + (rem & 7);
        pool[3456 + bf3 * 1152 + row * 72 + col] = (col == 64) ? 1.f : 0.f;
    }
    __syncthreads();

    float C[4][3][4];
    #pragma unroll
    for (int mt = 0; mt < 4; mt++)
        #pragma unroll
        for (int nt = 0; nt < 3; nt++)
            #pragma unroll
            for (int i = 0; i < 4; i++) C[mt][nt][i] = 0.f;
    const int nts = (w == 3) ? 3 : 2;
    const int e0  = w * 16;

    auto load_tile = [&](int t, int bf3){
        const long l0 = Lbase + (long)t * 16;
        const float* src = (w < 2) ? kglob : vglob;
        const u32 dbase = sb + ((w < 2 ? 0 : 3456) + bf3 * 1152) * 4;
        #pragma unroll
        for (int i = 0; i < 4; i++){
            int slot = lane + 32 * i;
            int r = (w & 1) * 8 + (slot >> 4);
            int ch = slot & 15;
            cpa16(dbase + (u32)(r * 72 + ch * 4) * 4, src + (l0 + r) * 1024 + ch * 4);
        }
        cp_commit();
    };

    load_tile(0, 0);

    for (int t = 0; t < 64; t++){
        if (t + 1 < 64){ load_tile(t + 1, (t + 1) % 3); cp_wait1(); }
        else cp_wait0();
        __syncthreads();

        float* kbuf = pool + (t % 3) * 1152;
        const float* vbuf = pool + 3456 + (t % 3) * 1152;

        {
            const int row = tid >> 3, sub = tid & 7;
            float* rowp = kbuf + row * 72 + sub * 8;
            float4 fa = *(float4*)rowp;
            float4 fb = *(float4*)(rowp + 4);
            float v0 = ex2(cT * ((fa.x < 0.f) ? -20.f : fa.x));
            float v1 = ex2(cT * ((fa.y < 0.f) ? -20.f : fa.y));
            float v2 = ex2(cT * ((fa.z < 0.f) ? -20.f : fa.z));
            float v3 = ex2(cT * ((fa.w < 0.f) ? -20.f : fa.w));
            float v4 = ex2(cT * ((fb.x < 0.f) ? -20.f : fb.x));
            float v5 = ex2(cT * ((fb.y < 0.f) ? -20.f : fb.y));
            float v6 = ex2(cT * ((fb.z < 0.f) ? -20.f : fb.z));
            float v7 = ex2(cT * ((fb.w < 0.f) ? -20.f : fb.w));
            float sm = ((v0 + v1) + (v2 + v3)) + ((v4 + v5) + (v6 + v7));
            sm += __shfl_xor_sync(FULL, sm, 1);
            sm += __shfl_xor_sync(FULL, sm, 2);
            sm += __shfl_xor_sync(FULL, sm, 4);
            float rs = frcp(sm);
            uint4 oa, ob;
            oa.x = totf32(v0 * rs); oa.y = totf32(v1 * rs);
            oa.z = totf32(v2 * rs); oa.w = totf32(v3 * rs);
            ob.x = totf32(v4 * rs); ob.y = totf32(v5 * rs);
            ob.z = totf32(v6 * rs); ob.w = totf32(v7 * rs);
            *(uint4*)rowp = oa;
            *(uint4*)(rowp + 4) = ob;
        }
        __syncthreads();

        {
            const u32* kB = (const u32*)kbuf;
            u32 bf[2][3][2];
            #pragma unroll
            for (int kt = 0; kt < 2; kt++)
                #pragma unroll
                for (int nt = 0; nt < 3; nt++)
                    if (nt < nts){
                        float b0 = vbuf[(kt * 8 + tig) * 72 + e0 + nt * 8 + g];
                        float b1 = vbuf[(kt * 8 + tig + 4) * 72 + e0 + nt * 8 + g];
                        bf[kt][nt][0] = totf32(b0);
                        bf[kt][nt][1] = totf32(b1);
                    }
            #pragma unroll
            for (int mt = 0; mt < 4; mt++){
                #pragma unroll
                for (int kt = 0; kt < 2; kt++){
                    u32 a0 = kB[(kt * 8 + tig) * 72 + mt * 16 + g];
                    u32 a1 = kB[(kt * 8 + tig) * 72 + mt * 16 + g + 8];
                    u32 a2 = kB[(kt * 8 + tig + 4) * 72 + mt * 16 + g];
                    u32 a3 = kB[(kt * 8 + tig + 4) * 72 + mt * 16 + g + 8];
                    #pragma unroll
                    for (int nt = 0; nt < 3; nt++)
                        if (nt < nts) MMA_TF32(C[mt][nt], a0, a1, a2, a3,
                                               bf[kt][nt][0], bf[kt][nt][1]);
                }
            }
        }
    }

    float* Mp = g_Mp + (long)bx * 4096;
    #pragma unroll
    for (int mt = 0; mt < 4; mt++){
        #pragma unroll
        for (int nt = 0; nt < 3; nt++){
            if (nt >= nts) continue;
            if (w == 3 && nt == 2){
                if (tig == 0){
                    g_Sp[bx * 64 + mt * 16 + g]     = C[mt][2][0];
                    g_Sp[bx * 64 + mt * 16 + g + 8] = C[mt][2][2];
                }
            } else {
                const int e = e0 + nt * 8 + 2 * tig;
                *(float2*)(Mp + (mt * 16 + g) * 64 + e)
                    = make_float2(C[mt][nt][0], C[mt][nt][1]);
                *(float2*)(Mp + (mt * 16 + g + 8) * 64 + e)
                    = make_float2(C[mt][nt][2], C[mt][nt][3]);
            }
        }
    }
}

// =====================================================================
// out_mma v4: M as persistent tf32 SMEM image (no BF registers).
// grid 512 (4 CTAs/bh, 1024 rows = 16 tiles of 64), block 128,
// ~100 regs -> 4 CTAs/SM. Warp w owns rows [16w,16w+16); fused softmax
// into A fragments; B fragments = plain LDS.32 from sMt (pre-cvt'd).
// Dynamic smem: sMt u32[64*68] | tiles float[2][64*68] | sSh[64].
// =====================================================================
#define OUT_SMEM (17408 * 3 + 256)

__global__ __launch_bounds__(128) void out_mma(
    const float* __restrict__ Qp, float* __restrict__ Out,
    const float* __restrict__ delta)
{
    extern __shared__ char osm[];
    u32*   sMt   = (u32*)osm;                       // [64*68] tf32 bits
    float* tiles = (float*)(osm + 17408);           // [2][64*68]
    float* sSh   = (float*)(osm + 17408 * 3);       // [64]

    const int bx   = blockIdx.x;
    const int bh   = bx >> 2;
    const int b    = bh >> 4, h = bh & 15;
    const int tid  = threadIdx.x;
    const int w    = tid >> 5, lane = tid & 31;
    const int g    = lane >> 2, tig = lane & 3;

    const float cT = get_cT(delta);
    const long cbase = ((long)b * 4096L) * 1024L + h * 64L;
    const long Lbase = (long)(bx & 3) * 1024;
    const u32 sb_tiles = (u32)__cvta_generic_to_shared(tiles);

    auto load_tile = [&](int t, int buf){
        const long l0 = Lbase + (long)t * 64;
        const u32 dbase = sb_tiles + (u32)(buf * 4352) * 4;
        #pragma unroll
        for (int i = 0; i < 8; i++){
            int slot = tid + 128 * i;          // 0..1023
            int r = slot >> 4, ch = slot & 15;
            cpa16(dbase + (u32)(r * 68 + ch * 4) * 4, Qp + cbase + (l0 + r) * 1024 + ch * 4);
        }
        cp_commit();
    };

    load_tile(0, 0);   // overlap tile 0 loads with M init

    if (tid < 64){
        float s = 0.f;
        #pragma unroll
        for (int p = 0; p < 4; p++) s += g_Sp[(bh * 4 + p) * 64 + tid];
        sSh[tid] = s;
    }
    // sum 4 M partials -> tf32 bits into sMt[d*68 + e]
    for (int i = tid; i < 1024; i += 128){
        const int d = i >> 4, c4 = (i & 15) * 4;
        float4 a = make_float4(0.f, 0.f, 0.f, 0.f);
        #pragma unroll
        for (int p = 0; p < 4; p++){
            float4 v = *(const float4*)(g_Mp + (long)(bh * 4 + p) * 4096 + d * 64 + c4);
            a.x += v.x; a.y += v.y; a.z += v.z; a.w += v.w;
        }
        uint4 o;
        o.x = totf32(a.x); o.y = totf32(a.y); o.z = totf32(a.z); o.w = totf32(a.w);
        *(uint4*)(sMt + d * 68 + c4) = o;
    }
    __syncthreads();

    float s_reg[16];
    #pragma unroll
    for (int j = 0; j < 16; j++) s_reg[j] = sSh[tig + 4 * j];

    int buf = 0;
    for (int t = 0; t < 16; t++){
        if (t + 1 < 16){ load_tile(t + 1, buf ^ 1); cp_wait1(); }
        else cp_wait0();
        __syncthreads();

        const float* r0p = tiles + buf * 4352 + (16 * w + g) * 68;
        const float* r1p = r0p + 8 * 68;

        float C[8][4];
        #pragma unroll
        for (int nt = 0; nt < 8; nt++)
            #pragma unroll
            for (int i = 0; i < 4; i++) C[nt][i] = 0.f;

        float sm0 = 0.f, u0 = 0.f, sm1 = 0.f, u1 = 0.f;

        #pragma unroll
        for (int kt = 0; kt < 8; kt++){
            float x0 = r0p[kt * 8 + tig];
            float x1 = r1p[kt * 8 + tig];
            float x2 = r0p[kt * 8 + tig + 4];
            float x3 = r1p[kt * 8 + tig + 4];
            float e0v = ex2(cT * ((x0 < 0.f) ? -20.f : x0));
            float e1v = ex2(cT * ((x1 < 0.f) ? -20.f : x1));
            float e2v = ex2(cT * ((x2 < 0.f) ? -20.f : x2));
            float e3v = ex2(cT * ((x3 < 0.f) ? -20.f : x3));
            sm0 += e0v + e2v;
            sm1 += e1v + e3v;
            u0 = fmaf(e0v, s_reg[2 * kt], fmaf(e2v, s_reg[2 * kt + 1], u0));
            u1 = fmaf(e1v, s_reg[2 * kt], fmaf(e3v, s_reg[2 * kt + 1], u1));
            u32 a0 = totf32(e0v), a1 = totf32(e1v);
            u32 a2 = totf32(e2v), a3 = totf32(e3v);
            const u32* b0p = sMt + (kt * 8 + tig) * 68 + g;
            const u32* b1p = sMt + (kt * 8 + tig + 4) * 68 + g;
            #pragma unroll
            for (int nt = 0; nt < 8; nt++)
                MMA_TF32(C[nt], a0, a1, a2, a3, b0p[nt * 8], b1p[nt * 8]);
        }

        #pragma unroll
        for (int o = 1; o <= 2; o <<= 1){
            sm0 += __shfl_xor_sync(FULL, sm0, o);
            u0  += __shfl_xor_sync(FULL, u0,  o);
            sm1 += __shfl_xor_sync(FULL, sm1, o);
            u1  += __shfl_xor_sync(FULL, u1,  o);
        }
        const float gv0 = frcp(u0 + 1e-6f * sm0);
        const float gv1 = frcp(u1 + 1e-6f * sm1);

        const long l0 = Lbase + (long)t * 64 + 16 * w;
        float* o0 = Out + cbase + (l0 + g) * 1024 + 2 * tig;
        float* o1 = Out + cbase + (l0 + g + 8) * 1024 + 2 * tig;
        #pragma unroll
        for (int nt = 0; nt < 8; nt++){
            *(float2*)(o0 + nt * 8) = make_float2(C[nt][0] * gv0, C[nt][1] * gv0);
            *(float2*)(o1 + nt * 8) = make_float2(C[nt][2] * gv1, C[nt][3] * gv1);
        }
        __syncthreads();
        buf ^= 1;
    }
}

extern "C" void kernel_launch(void* const* d_in, const int* in_sizes, int n_in,
                              void* d_out, int out_size)
{
    const float* Q     = (const float*)d_in[0];
    const float* K     = (const float*)d_in[1];
    const float* V     = (const float*)d_in[2];
    const float* delta = (const float*)d_in[3];
    float* Out = (float*)d_out;

    kv_mma<<<512, 128>>>(K, V, delta);
    cudaFuncSetAttribute(out_mma, cudaFuncAttributeMaxDynamicSharedMemorySize, OUT_SMEM);
    out_mma<<<512, 128, OUT_SMEM>>>(Q, Out, delta);
}

// round 14
// speedup vs baseline: 1.0127x; 1.0127x over previous
#include <cuda_runtime.h>
#include <cstdint>

typedef unsigned long long u64;
typedef unsigned int u32;
#define FULL 0xFFFFFFFFu

__device__ __forceinline__ float ex2(float x){
    float r; asm("ex2.approx.f32 %0,%1;" : "=f"(r) : "f"(x)); return r;
}
__device__ __forceinline__ float frcp(float x){
    float r; asm("rcp.approx.f32 %0,%1;" : "=f"(r) : "f"(x)); return r;
}
__device__ __forceinline__ u32 totf32(float x){
    u32 r; asm("cvt.rna.tf32.f32 %0,%1;" : "=r"(r) : "f"(x)); return r;
}
__device__ __forceinline__ void cpa16(u32 dst, const void* src){
    asm volatile("cp.async.cg.shared.global [%0], [%1], 16;" :: "r"(dst), "l"(src));
}
__device__ __forceinline__ void cp_commit(){ asm volatile("cp.async.commit_group;"); }
__device__ __forceinline__ void cp_wait1(){ asm volatile("cp.async.wait_group 1;"); }
__device__ __forceinline__ void cp_wait0(){ asm volatile("cp.async.wait_group 0;"); }

// per-CTA partials: [bh*4 + q4]
__device__ float g_Mp[512 * 4096];
__device__ float g_Sp[512 * 64];

__device__ __forceinline__ float get_cT(const float* __restrict__ delta){
    float d = delta[0];
    float t = (d > 20.f) ? d : log1pf(expf(d));
    return 1.44269504088896f / t;
}

#define MMA_TF32(C, a0,a1,a2,a3, b0,b1) \
    asm("mma.sync.aligned.m16n8k8.row.col.f32.tf32.tf32.f32 " \
        "{%0,%1,%2,%3},{%4,%5,%6,%7},{%8,%9},{%0,%1,%2,%3};" \
        : "+f"((C)[0]),"+f"((C)[1]),"+f"((C)[2]),"+f"((C)[3]) \
        : "r"(a0),"r"(a1),"r"(a2),"r"(a3), "r"(b0),"r"(b1))

// =====================================================================
// kv_mma v2: 32-row tiles (32 tiles), double-buffered, 2 barriers/tile.
// Loads for t+1 issued right after sync#1 (safe: sync#1 proves all
// warps consumed tile t-1, the overwrite target).
// grid 512, block 128, 4 CTAs/SM.
// =====================================================================
__global__ __launch_bounds__(128, 4) void kv_mma(
    const float* __restrict__ Kp, const float* __restrict__ Vp,
    const float* __restrict__ delta)
{
    __shared__ float pool[9216];   // k: 2x2304 @0, v: 2x2304 @4608

    const int bx   = blockIdx.x;
    const int bh   = bx >> 2;
    const int b    = bh >> 4, h = bh & 15;
    const int tid  = threadIdx.x;
    const int w    = tid >> 5, lane = tid & 31;
    const int g    = lane >> 2, tig = lane & 3;

    const float cT = get_cT(delta);
    const long cbase = ((long)b * 4096L) * 1024L + h * 64L;
    const float* kglob = Kp + cbase;
    const float* vglob = Vp + cbase;
    const long Lbase = (long)(bx & 3) * 1024;

    const u32 sb = (u32)__cvta_generic_to_shared(pool);

    // ones column at e=64 (cols 65-71 zero) in both v buffers
    for (int idx = tid; idx < 512; idx += 128){
        int bf2 = idx >> 8, rem = idx & 255;
        int row = rem >> 3, col = 64 + (rem & 7);
        pool[4608 + bf2 * 2304 + row * 72 + col] = (col == 64) ? 1.f : 0.f;
    }
    __syncthreads();

    float C[4][3][4];
    #pragma unroll
    for (int mt = 0; mt < 4; mt++)
        #pragma unroll
        for (int nt = 0; nt < 3; nt++)
            #pragma unroll
            for (int i = 0; i < 4; i++) C[mt][nt][i] = 0.f;
    const int nts = (w == 3) ? 3 : 2;
    const int e0  = w * 16;

    // per warp: 16 rows x 16 chunks = 256 chunks = 8 cpa16/thread
    auto load_tile = [&](int t, int bf2){
        const long l0 = Lbase + (long)t * 32;
        const float* src = (w < 2) ? kglob : vglob;
        const u32 dbase = sb + ((w < 2 ? 0 : 4608) + bf2 * 2304) * 4;
        const int rbase = (w & 1) * 16;
        #pragma unroll
        for (int i = 0; i < 8; i++){
            int slot = lane + 32 * i;          // 0..255
            int r = rbase + (slot >> 4);
            int ch = slot & 15;
            cpa16(dbase + (u32)(r * 72 + ch * 4) * 4, src + (l0 + r) * 1024 + ch * 4);
        }
        cp_commit();
    };

    load_tile(0, 0);

    int buf = 0;
    for (int t = 0; t < 32; t++){
        cp_wait0();
        __syncthreads();                       // sync#1: tile t resident, t-1 consumed
        if (t + 1 < 32) load_tile(t + 1, buf ^ 1);

        float* kbuf = pool + buf * 2304;
        const float* vbuf = pool + 4608 + buf * 2304;

        // ---- Phase B: 4 threads/row over 32 rows; softmax -> tf32 in place ----
        {
            const int row = tid >> 2, sub = tid & 3;
            float* rowp = kbuf + row * 72 + sub * 16;
            float4 fa = *(float4*)rowp;
            float4 fb = *(float4*)(rowp + 4);
            float4 fc = *(float4*)(rowp + 8);
            float4 fd = *(float4*)(rowp + 12);
            float v0 = ex2(cT * ((fa.x < 0.f) ? -20.f : fa.x));
            float v1 = ex2(cT * ((fa.y < 0.f) ? -20.f : fa.y));
            float v2 = ex2(cT * ((fa.z < 0.f) ? -20.f : fa.z));
            float v3 = ex2(cT * ((fa.w < 0.f) ? -20.f : fa.w));
            float v4 = ex2(cT * ((fb.x < 0.f) ? -20.f : fb.x));
            float v5 = ex2(cT * ((fb.y < 0.f) ? -20.f : fb.y));
            float v6 = ex2(cT * ((fb.z < 0.f) ? -20.f : fb.z));
            float v7 = ex2(cT * ((fb.w < 0.f) ? -20.f : fb.w));
            float v8 = ex2(cT * ((fc.x < 0.f) ? -20.f : fc.x));
            float v9 = ex2(cT * ((fc.y < 0.f) ? -20.f : fc.y));
            float vA = ex2(cT * ((fc.z < 0.f) ? -20.f : fc.z));
            float vB = ex2(cT * ((fc.w < 0.f) ? -20.f : fc.w));
            float vC = ex2(cT * ((fd.x < 0.f) ? -20.f : fd.x));
            float vD = ex2(cT * ((fd.y < 0.f) ? -20.f : fd.y));
            float vE = ex2(cT * ((fd.z < 0.f) ? -20.f : fd.z));
            float vF = ex2(cT * ((fd.w < 0.f) ? -20.f : fd.w));
            float sm = (((v0 + v1) + (v2 + v3)) + ((v4 + v5) + (v6 + v7)))
                     + (((v8 + v9) + (vA + vB)) + ((vC + vD) + (vE + vF)));
            sm += __shfl_xor_sync(FULL, sm, 1);
            sm += __shfl_xor_sync(FULL, sm, 2);
            float rs = frcp(sm);
            uint4 oa, ob, oc, od;
            oa.x = totf32(v0 * rs); oa.y = totf32(v1 * rs);
            oa.z = totf32(v2 * rs); oa.w = totf32(v3 * rs);
            ob.x = totf32(v4 * rs); ob.y = totf32(v5 * rs);
            ob.z = totf32(v6 * rs); ob.w = totf32(v7 * rs);
            oc.x = totf32(v8 * rs); oc.y = totf32(v9 * rs);
            oc.z = totf32(vA * rs); oc.w = totf32(vB * rs);
            od.x = totf32(vC * rs); od.y = totf32(vD * rs);
            od.z = totf32(vE * rs); od.w = totf32(vF * rs);
            *(uint4*)rowp        = oa;
            *(uint4*)(rowp + 4)  = ob;
            *(uint4*)(rowp + 8)  = oc;
            *(uint4*)(rowp + 12) = od;
        }
        __syncthreads();                       // sync#2: converted tile ready

        // ---- Phase C: 4 k-tiles of 8 rows; MMA ----
        {
            const u32* kB = (const u32*)kbuf;
            u32 bf[4][3][2];
            #pragma unroll
            for (int kt = 0; kt < 4; kt++)
                #pragma unroll
                for (int nt = 0; nt < 3; nt++)
                    if (nt < nts){
                        float b0 = vbuf[(kt * 8 + tig) * 72 + e0 + nt * 8 + g];
                        float b1 = vbuf[(kt * 8 + tig + 4) * 72 + e0 + nt * 8 + g];
                        bf[kt][nt][0] = totf32(b0);
                        bf[kt][nt][1] = totf32(b1);
                    }
            #pragma unroll
            for (int mt = 0; mt < 4; mt++){
                #pragma unroll
                for (int kt = 0; kt < 4; kt++){
                    u32 a0 = kB[(kt * 8 + tig) * 72 + mt * 16 + g];
                    u32 a1 = kB[(kt * 8 + tig) * 72 + mt * 16 + g + 8];
                    u32 a2 = kB[(kt * 8 + tig + 4) * 72 + mt * 16 + g];
                    u32 a3 = kB[(kt * 8 + tig + 4) * 72 + mt * 16 + g + 8];
                    #pragma unroll
                    for (int nt = 0; nt < 3; nt++)
                        if (nt < nts) MMA_TF32(C[mt][nt], a0, a1, a2, a3,
                                               bf[kt][nt][0], bf[kt][nt][1]);
                }
            }
        }
        buf ^= 1;
    }

    float* Mp = g_Mp + (long)bx * 4096;
    #pragma unroll
    for (int mt = 0; mt < 4; mt++){
        #pragma unroll
        for (int nt = 0; nt < 3; nt++){
            if (nt >= nts) continue;
            if (w == 3 && nt == 2){
                if (tig == 0){
                    g_Sp[bx * 64 + mt * 16 + g]     = C[mt][2][0];
                    g_Sp[bx * 64 + mt * 16 + g + 8] = C[mt][2][2];
                }
            } else {
                const int e = e0 + nt * 8 + 2 * tig;
                *(float2*)(Mp + (mt * 16 + g) * 64 + e)
                    = make_float2(C[mt][nt][0], C[mt][nt][1]);
                *(float2*)(Mp + (mt * 16 + g + 8) * 64 + e)
                    = make_float2(C[mt][nt][2], C[mt][nt][3]);
            }
        }
    }
}

// =====================================================================
// out_mma: R12 version (measured 73.5us) — fused softmax into A
// fragments, M B-fragments register-resident. grid 1024 (8 CTAs/bh),
// block 128, 2 CTAs/SM.
// =====================================================================
__global__ __launch_bounds__(128, 2) void out_mma(
    const float* __restrict__ Qp, float* __restrict__ Out,
    const float* __restrict__ delta)
{
    __shared__ float pool[8704];   // init: sM[64][68]; then 2 tile buffers [64][68]
    __shared__ float sSh[64];

    const int bx   = blockIdx.x;
    const int bh   = bx >> 3;
    const int b    = bh >> 4, h = bh & 15;
    const int tid  = threadIdx.x;
    const int w    = tid >> 5, lane = tid & 31;
    const int g    = lane >> 2, tig = lane & 3;

    const float cT = get_cT(delta);
    const long cbase = ((long)b * 4096L) * 1024L + h * 64L;
    const long Lbase = (long)(bx & 7) * 512;
    const u32 sb = (u32)__cvta_generic_to_shared(pool);

    if (tid < 64){
        float s = 0.f;
        #pragma unroll
        for (int p = 0; p < 4; p++) s += g_Sp[(bh * 4 + p) * 64 + tid];
        sSh[tid] = s;
    }
    for (int i = tid; i < 1024; i += 128){
        const int d = i >> 4, c4 = (i & 15) * 4;
        float4 a = make_float4(0.f, 0.f, 0.f, 0.f);
        #pragma unroll
        for (int p = 0; p < 4; p++){
            float4 v = *(const float4*)(g_Mp + (long)(bh * 4 + p) * 4096 + d * 64 + c4);
            a.x += v.x; a.y += v.y; a.z += v.z; a.w += v.w;
        }
        *(float4*)(pool + d * 68 + c4) = a;
    }
    __syncthreads();

    u32 BF[8][8][2];
    #pragma unroll
    for (int kt = 0; kt < 8; kt++)
        #pragma unroll
        for (int nt = 0; nt < 8; nt++){
            BF[kt][nt][0] = totf32(pool[(kt * 8 + tig)     * 68 + nt * 8 + g]);
            BF[kt][nt][1] = totf32(pool[(kt * 8 + tig + 4) * 68 + nt * 8 + g]);
        }
    float s_reg[16];
    #pragma unroll
    for (int j = 0; j < 16; j++) s_reg[j] = sSh[tig + 4 * j];
    __syncthreads();

    auto load_tile = [&](int t, int buf){
        const long l0 = Lbase + (long)t * 64;
        const u32 dbase = sb + (u32)(buf * 4352) * 4;
        #pragma unroll
        for (int i = 0; i < 8; i++){
            int slot = tid + 128 * i;
            int r = slot >> 4, ch = slot & 15;
            cpa16(dbase + (u32)(r * 68 + ch * 4) * 4, Qp + cbase + (l0 + r) * 1024 + ch * 4);
        }
        cp_commit();
    };

    load_tile(0, 0);

    int buf = 0;
    for (int t = 0; t < 8; t++){
        if (t + 1 < 8){ load_tile(t + 1, buf ^ 1); cp_wait1(); }
        else cp_wait0();
        __syncthreads();

        const float* r0p = pool + buf * 4352 + (16 * w + g) * 68;
        const float* r1p = r0p + 8 * 68;

        float C[8][4];
        #pragma unroll
        for (int nt = 0; nt < 8; nt++)
            #pragma unroll
            for (int i = 0; i < 4; i++) C[nt][i] = 0.f;

        float sm0 = 0.f, u0 = 0.f, sm1 = 0.f, u1 = 0.f;

        #pragma unroll
        for (int kt = 0; kt < 8; kt++){
            float x0 = r0p[kt * 8 + tig];
            float x1 = r1p[kt * 8 + tig];
            float x2 = r0p[kt * 8 + tig + 4];
            float x3 = r1p[kt * 8 + tig + 4];
            float e0v = ex2(cT * ((x0 < 0.f) ? -20.f : x0));
            float e1v = ex2(cT * ((x1 < 0.f) ? -20.f : x1));
            float e2v = ex2(cT * ((x2 < 0.f) ? -20.f : x2));
            float e3v = ex2(cT * ((x3 < 0.f) ? -20.f : x3));
            sm0 += e0v + e2v;
            sm1 += e1v + e3v;
            u0 = fmaf(e0v, s_reg[2 * kt], fmaf(e2v, s_reg[2 * kt + 1], u0));
            u1 = fmaf(e1v, s_reg[2 * kt], fmaf(e3v, s_reg[2 * kt + 1], u1));
            u32 a0 = totf32(e0v), a1 = totf32(e1v);
            u32 a2 = totf32(e2v), a3 = totf32(e3v);
            #pragma unroll
            for (int nt = 0; nt < 8; nt++)
                MMA_TF32(C[nt], a0, a1, a2, a3, BF[kt][nt][0], BF[kt][nt][1]);
        }

        #pragma unroll
        for (int o = 1; o <= 2; o <<= 1){
            sm0 += __shfl_xor_sync(FULL, sm0, o);
            u0  += __shfl_xor_sync(FULL, u0,  o);
            sm1 += __shfl_xor_sync(FULL, sm1, o);
            u1  += __shfl_xor_sync(FULL, u1,  o);
        }
        const float gv0 = frcp(u0 + 1e-6f * sm0);
        const float gv1 = frcp(u1 + 1e-6f * sm1);

        const long l0 = Lbase + (long)t * 64 + 16 * w;
        float* o0 = Out + cbase + (l0 + g) * 1024 + 2 * tig;
        float* o1 = Out + cbase + (l0 + g + 8) * 1024 + 2 * tig;
        #pragma unroll
        for (int nt = 0; nt < 8; nt++){
            *(float2*)(o0 + nt * 8) = make_float2(C[nt][0] * gv0, C[nt][1] * gv0);
            *(float2*)(o1 + nt * 8) = make_float2(C[nt][2] * gv1, C[nt][3] * gv1);
        }
        __syncthreads();
        buf ^= 1;
    }
}

extern "C" void kernel_launch(void* const* d_in, const int* in_sizes, int n_in,
                              void* d_out, int out_size)
{
    const float* Q     = (const float*)d_in[0];
    const float* K     = (const float*)d_in[1];
    const float* V     = (const float*)d_in[2];
    const float* delta = (const float*)d_in[3];
    float* Out = (float*)d_out;

    kv_mma<<<512, 128>>>(K, V, delta);
    out_mma<<<1024, 128>>>(Q, Out, delta);
}

// round 15
// speedup vs baseline: 1.0565x; 1.0433x over previous
#include <cuda_runtime.h>
#include <cstdint>

typedef unsigned long long u64;
typedef unsigned int u32;
#define FULL 0xFFFFFFFFu

__device__ __forceinline__ float ex2(float x){
    float r; asm("ex2.approx.f32 %0,%1;" : "=f"(r) : "f"(x)); return r;
}
__device__ __forceinline__ float frcp(float x){
    float r; asm("rcp.approx.f32 %0,%1;" : "=f"(r) : "f"(x)); return r;
}
__device__ __forceinline__ u32 totf32(float x){
    u32 r; asm("cvt.rna.tf32.f32 %0,%1;" : "=r"(r) : "f"(x)); return r;
}
__device__ __forceinline__ void cpa16(u32 dst, const void* src){
    asm volatile("cp.async.cg.shared.global [%0], [%1], 16;" :: "r"(dst), "l"(src));
}
__device__ __forceinline__ void cp_commit(){ asm volatile("cp.async.commit_group;"); }
__device__ __forceinline__ void cp_wait1(){ asm volatile("cp.async.wait_group 1;"); }
__device__ __forceinline__ void cp_wait0(){ asm volatile("cp.async.wait_group 0;"); }

// per-CTA partials: [bh*4 + q4]
__device__ float g_Mp[512 * 4096];
__device__ float g_Sp[512 * 64];

__device__ __forceinline__ float get_cT(const float* __restrict__ delta){
    float d = delta[0];
    float t = (d > 20.f) ? d : log1pf(expf(d));
    return 1.44269504088896f / t;
}

#define MMA_TF32(C, a0,a1,a2,a3, b0,b1) \
    asm("mma.sync.aligned.m16n8k8.row.col.f32.tf32.tf32.f32 " \
        "{%0,%1,%2,%3},{%4,%5,%6,%7},{%8,%9},{%0,%1,%2,%3};" \
        : "+f"((C)[0]),"+f"((C)[1]),"+f"((C)[2]),"+f"((C)[3]) \
        : "r"(a0),"r"(a1),"r"(a2),"r"(a3), "r"(b0),"r"(b1))

// =====================================================================
// kv_mma: unchanged from round 14 (32-row tiles, 2 barriers/tile).
// =====================================================================
__global__ __launch_bounds__(128, 4) void kv_mma(
    const float* __restrict__ Kp, const float* __restrict__ Vp,
    const float* __restrict__ delta)
{
    __shared__ float pool[9216];   // k: 2x2304 @0, v: 2x2304 @4608

    const int bx   = blockIdx.x;
    const int bh   = bx >> 2;
    const int b    = bh >> 4, h = bh & 15;
    const int tid  = threadIdx.x;
    const int w    = tid >> 5, lane = tid & 31;
    const int g    = lane >> 2, tig = lane & 3;

    const float cT = get_cT(delta);
    const long cbase = ((long)b * 4096L) * 1024L + h * 64L;
    const float* kglob = Kp + cbase;
    const float* vglob = Vp + cbase;
    const long Lbase = (long)(bx & 3) * 1024;

    const u32 sb = (u32)__cvta_generic_to_shared(pool);

    for (int idx = tid; idx < 512; idx += 128){
        int bf2 = idx >> 8, rem = idx & 255;
        int row = rem >> 3, col = 64 + (rem & 7);
        pool[4608 + bf2 * 2304 + row * 72 + col] = (col == 64) ? 1.f : 0.f;
    }
    __syncthreads();

    float C[4][3][4];
    #pragma unroll
    for (int mt = 0; mt < 4; mt++)
        #pragma unroll
        for (int nt = 0; nt < 3; nt++)
            #pragma unroll
            for (int i = 0; i < 4; i++) C[mt][nt][i] = 0.f;
    const int nts = (w == 3) ? 3 : 2;
    const int e0  = w * 16;

    auto load_tile = [&](int t, int bf2){
        const long l0 = Lbase + (long)t * 32;
        const float* src = (w < 2) ? kglob : vglob;
        const u32 dbase = sb + ((w < 2 ? 0 : 4608) + bf2 * 2304) * 4;
        const int rbase = (w & 1) * 16;
        #pragma unroll
        for (int i = 0; i < 8; i++){
            int slot = lane + 32 * i;
            int r = rbase + (slot >> 4);
            int ch = slot & 15;
            cpa16(dbase + (u32)(r * 72 + ch * 4) * 4, src + (l0 + r) * 1024 + ch * 4);
        }
        cp_commit();
    };

    load_tile(0, 0);

    int buf = 0;
    for (int t = 0; t < 32; t++){
        cp_wait0();
        __syncthreads();
        if (t + 1 < 32) load_tile(t + 1, buf ^ 1);

        float* kbuf = pool + buf * 2304;
        const float* vbuf = pool + 4608 + buf * 2304;

        {
            const int row = tid >> 2, sub = tid & 3;
            float* rowp = kbuf + row * 72 + sub * 16;
            float4 fa = *(float4*)rowp;
            float4 fb = *(float4*)(rowp + 4);
            float4 fc = *(float4*)(rowp + 8);
            float4 fd = *(float4*)(rowp + 12);
            float v0 = ex2(cT * ((fa.x < 0.f) ? -20.f : fa.x));
            float v1 = ex2(cT * ((fa.y < 0.f) ? -20.f : fa.y));
            float v2 = ex2(cT * ((fa.z < 0.f) ? -20.f : fa.z));
            float v3 = ex2(cT * ((fa.w < 0.f) ? -20.f : fa.w));
            float v4 = ex2(cT * ((fb.x < 0.f) ? -20.f : fb.x));
            float v5 = ex2(cT * ((fb.y < 0.f) ? -20.f : fb.y));
            float v6 = ex2(cT * ((fb.z < 0.f) ? -20.f : fb.z));
            float v7 = ex2(cT * ((fb.w < 0.f) ? -20.f : fb.w));
            float v8 = ex2(cT * ((fc.x < 0.f) ? -20.f : fc.x));
            float v9 = ex2(cT * ((fc.y < 0.f) ? -20.f : fc.y));
            float vA = ex2(cT * ((fc.z < 0.f) ? -20.f : fc.z));
            float vB = ex2(cT * ((fc.w < 0.f) ? -20.f : fc.w));
            float vC = ex2(cT * ((fd.x < 0.f) ? -20.f : fd.x));
            float vD = ex2(cT * ((fd.y < 0.f) ? -20.f : fd.y));
            float vE = ex2(cT * ((fd.z < 0.f) ? -20.f : fd.z));
            float vF = ex2(cT * ((fd.w < 0.f) ? -20.f : fd.w));
            float sm = (((v0 + v1) + (v2 + v3)) + ((v4 + v5) + (v6 + v7)))
                     + (((v8 + v9) + (vA + vB)) + ((vC + vD) + (vE + vF)));
            sm += __shfl_xor_sync(FULL, sm, 1);
            sm += __shfl_xor_sync(FULL, sm, 2);
            float rs = frcp(sm);
            uint4 oa, ob, oc, od;
            oa.x = totf32(v0 * rs); oa.y = totf32(v1 * rs);
            oa.z = totf32(v2 * rs); oa.w = totf32(v3 * rs);
            ob.x = totf32(v4 * rs); ob.y = totf32(v5 * rs);
            ob.z = totf32(v6 * rs); ob.w = totf32(v7 * rs);
            oc.x = totf32(v8 * rs); oc.y = totf32(v9 * rs);
            oc.z = totf32(vA * rs); oc.w = totf32(vB * rs);
            od.x = totf32(vC * rs); od.y = totf32(vD * rs);
            od.z = totf32(vE * rs); od.w = totf32(vF * rs);
            *(uint4*)rowp        = oa;
            *(uint4*)(rowp + 4)  = ob;
            *(uint4*)(rowp + 8)  = oc;
            *(uint4*)(rowp + 12) = od;
        }
        __syncthreads();

        {
            const u32* kB = (const u32*)kbuf;
            u32 bf[4][3][2];
            #pragma unroll
            for (int kt = 0; kt < 4; kt++)
                #pragma unroll
                for (int nt = 0; nt < 3; nt++)
                    if (nt < nts){
                        float b0 = vbuf[(kt * 8 + tig) * 72 + e0 + nt * 8 + g];
                        float b1 = vbuf[(kt * 8 + tig + 4) * 72 + e0 + nt * 8 + g];
                        bf[kt][nt][0] = totf32(b0);
                        bf[kt][nt][1] = totf32(b1);
                    }
            #pragma unroll
            for (int mt = 0; mt < 4; mt++){
                #pragma unroll
                for (int kt = 0; kt < 4; kt++){
                    u32 a0 = kB[(kt * 8 + tig) * 72 + mt * 16 + g];
                    u32 a1 = kB[(kt * 8 + tig) * 72 + mt * 16 + g + 8];
                    u32 a2 = kB[(kt * 8 + tig + 4) * 72 + mt * 16 + g];
                    u32 a3 = kB[(kt * 8 + tig + 4) * 72 + mt * 16 + g + 8];
                    #pragma unroll
                    for (int nt = 0; nt < 3; nt++)
                        if (nt < nts) MMA_TF32(C[mt][nt], a0, a1, a2, a3,
                                               bf[kt][nt][0], bf[kt][nt][1]);
                }
            }
        }
        buf ^= 1;
    }

    float* Mp = g_Mp + (long)bx * 4096;
    #pragma unroll
    for (int mt = 0; mt < 4; mt++){
        #pragma unroll
        for (int nt = 0; nt < 3; nt++){
            if (nt >= nts) continue;
            if (w == 3 && nt == 2){
                if (tig == 0){
                    g_Sp[bx * 64 + mt * 16 + g]     = C[mt][2][0];
                    g_Sp[bx * 64 + mt * 16 + g + 8] = C[mt][2][2];
                }
            } else {
                const int e = e0 + nt * 8 + 2 * tig;
                *(float2*)(Mp + (mt * 16 + g) * 64 + e)
                    = make_float2(C[mt][nt][0], C[mt][nt][1]);
                *(float2*)(Mp + (mt * 16 + g + 8) * 64 + e)
                    = make_float2(C[mt][nt][2], C[mt][nt][3]);
            }
        }
    }
}

// =====================================================================
// out_mma v5: fully independent warps — per-warp double-buffered 16-row
// slices, per-warp cp.async groups, ZERO block barriers in the loop.
// grid 1024 (8 CTAs/bh, 512 rows), block 128, 2 CTAs/SM.
// Dynamic smem: sM f[64*68] | wbuf f[4][2][16][68] | sSh f[64].
// =====================================================================
#define SM_BYTES    17408
#define WBUF_BYTES  34816
#define OUT_SMEM    (SM_BYTES + WBUF_BYTES + 256)

__global__ __launch_bounds__(128, 2) void out_mma(
    const float* __restrict__ Qp, float* __restrict__ Out,
    const float* __restrict__ delta)
{
    extern __shared__ char osm[];
    float* sM   = (float*)osm;                         // [64*68], init only
    float* wall = (float*)(osm + SM_BYTES);            // [4][2][1088]
    float* sSh  = (float*)(osm + SM_BYTES + WBUF_BYTES);

    const int bx   = blockIdx.x;
    const int bh   = bx >> 3;
    const int b    = bh >> 4, h = bh & 15;
    const int tid  = threadIdx.x;
    const int w    = tid >> 5, lane = tid & 31;
    const int g    = lane >> 2, tig = lane & 3;

    const float cT = get_cT(delta);
    const long cbase = ((long)b * 4096L) * 1024L + h * 64L;
    const long Lbase = (long)(bx & 7) * 512;

    float* wbuf = wall + w * 2176;                     // this warp's 2 buffers
    const u32 wb = (u32)__cvta_generic_to_shared(wbuf);

    // per-warp tile load: 16 rows (global rows l0+16w .. +16) into buffer
    auto load_tile = [&](int t, int buf){
        const long l0 = Lbase + (long)t * 64 + 16 * w;
        const u32 dbase = wb + (u32)(buf * 1088) * 4;
        #pragma unroll
        for (int i = 0; i < 8; i++){
            int slot = lane + 32 * i;          // 0..255
            int r = slot >> 4, ch = slot & 15;
            cpa16(dbase + (u32)(r * 68 + ch * 4) * 4, Qp + cbase + (l0 + r) * 1024 + ch * 4);
        }
        cp_commit();
    };

    load_tile(0, 0);   // prefetch overlaps M init (disjoint smem regions)

    if (tid < 64){
        float s = 0.f;
        #pragma unroll
        for (int p = 0; p < 4; p++) s += g_Sp[(bh * 4 + p) * 64 + tid];
        sSh[tid] = s;
    }
    for (int i = tid; i < 1024; i += 128){
        const int d = i >> 4, c4 = (i & 15) * 4;
        float4 a = make_float4(0.f, 0.f, 0.f, 0.f);
        #pragma unroll
        for (int p = 0; p < 4; p++){
            float4 v = *(const float4*)(g_Mp + (long)(bh * 4 + p) * 4096 + d * 64 + c4);
            a.x += v.x; a.y += v.y; a.z += v.z; a.w += v.w;
        }
        *(float4*)(sM + d * 68 + c4) = a;
    }
    __syncthreads();   // sM/sSh ready (region never recycled — last barrier)

    u32 BF[8][8][2];
    #pragma unroll
    for (int kt = 0; kt < 8; kt++)
        #pragma unroll
        for (int nt = 0; nt < 8; nt++){
            BF[kt][nt][0] = totf32(sM[(kt * 8 + tig)     * 68 + nt * 8 + g]);
            BF[kt][nt][1] = totf32(sM[(kt * 8 + tig + 4) * 68 + nt * 8 + g]);
        }
    float s_reg[16];
    #pragma unroll
    for (int j = 0; j < 16; j++) s_reg[j] = sSh[tig + 4 * j];

    int buf = 0;
    for (int t = 0; t < 8; t++){
        if (t + 1 < 8){ load_tile(t + 1, buf ^ 1); cp_wait1(); }
        else cp_wait0();
        __syncwarp();

        const float* r0p = wbuf + buf * 1088 + g * 68;
        const float* r1p = r0p + 8 * 68;

        float C[8][4];
        #pragma unroll
        for (int nt = 0; nt < 8; nt++)
            #pragma unroll
            for (int i = 0; i < 4; i++) C[nt][i] = 0.f;

        float sm0 = 0.f, u0 = 0.f, sm1 = 0.f, u1 = 0.f;

        #pragma unroll
        for (int kt = 0; kt < 8; kt++){
            float x0 = r0p[kt * 8 + tig];
            float x1 = r1p[kt * 8 + tig];
            float x2 = r0p[kt * 8 + tig + 4];
            float x3 = r1p[kt * 8 + tig + 4];
            float e0v = ex2(cT * ((x0 < 0.f) ? -20.f : x0));
            float e1v = ex2(cT * ((x1 < 0.f) ? -20.f : x1));
            float e2v = ex2(cT * ((x2 < 0.f) ? -20.f : x2));
            float e3v = ex2(cT * ((x3 < 0.f) ? -20.f : x3));
            sm0 += e0v + e2v;
            sm1 += e1v + e3v;
            u0 = fmaf(e0v, s_reg[2 * kt], fmaf(e2v, s_reg[2 * kt + 1], u0));
            u1 = fmaf(e1v, s_reg[2 * kt], fmaf(e3v, s_reg[2 * kt + 1], u1));
            u32 a0 = totf32(e0v), a1 = totf32(e1v);
            u32 a2 = totf32(e2v), a3 = totf32(e3v);
            #pragma unroll
            for (int nt = 0; nt < 8; nt++)
                MMA_TF32(C[nt], a0, a1, a2, a3, BF[kt][nt][0], BF[kt][nt][1]);
        }

        #pragma unroll
        for (int o = 1; o <= 2; o <<= 1){
            sm0 += __shfl_xor_sync(FULL, sm0, o);
            u0  += __shfl_xor_sync(FULL, u0,  o);
            sm1 += __shfl_xor_sync(FULL, sm1, o);
            u1  += __shfl_xor_sync(FULL, u1,  o);
        }
        const float gv0 = frcp(u0 + 1e-6f * sm0);
        const float gv1 = frcp(u1 + 1e-6f * sm1);

        const long l0 = Lbase + (long)t * 64 + 16 * w;
        float* o0 = Out + cbase + (l0 + g) * 1024 + 2 * tig;
        float* o1 = Out + cbase + (l0 + g + 8) * 1024 + 2 * tig;
        #pragma unroll
        for (int nt = 0; nt < 8; nt++){
            *(float2*)(o0 + nt * 8) = make_float2(C[nt][0] * gv0, C[nt][1] * gv0);
            *(float2*)(o1 + nt * 8) = make_float2(C[nt][2] * gv1, C[nt][3] * gv1);
        }
        __syncwarp();
        buf ^= 1;
    }
}

extern "C" void kernel_launch(void* const* d_in, const int* in_sizes, int n_in,
                              void* d_out, int out_size)
{
    const float* Q     = (const float*)d_in[0];
    const float* K     = (const float*)d_in[1];
    const float* V     = (const float*)d_in[2];
    const float* delta = (const float*)d_in[3];
    float* Out = (float*)d_out;

    kv_mma<<<512, 128>>>(K, V, delta);
    cudaFuncSetAttribute(out_mma, cudaFuncAttributeMaxDynamicSharedMemorySize, OUT_SMEM);
    out_mma<<<1024, 128, OUT_SMEM>>>(Q, Out, delta);
}

// round 16
// speedup vs baseline: 1.0684x; 1.0112x over previous
#include <cuda_runtime.h>
#include <cstdint>

typedef unsigned long long u64;
typedef unsigned int u32;
#define FULL 0xFFFFFFFFu

__device__ __forceinline__ float ex2(float x){
    float r; asm("ex2.approx.f32 %0,%1;" : "=f"(r) : "f"(x)); return r;
}
__device__ __forceinline__ float frcp(float x){
    float r; asm("rcp.approx.f32 %0,%1;" : "=f"(r) : "f"(x)); return r;
}
__device__ __forceinline__ u32 totf32(float x){
    u32 r; asm("cvt.rna.tf32.f32 %0,%1;" : "=r"(r) : "f"(x)); return r;
}
__device__ __forceinline__ void cpa16(u32 dst, const void* src){
    asm volatile("cp.async.cg.shared.global [%0], [%1], 16;" :: "r"(dst), "l"(src));
}
__device__ __forceinline__ void cp_commit(){ asm volatile("cp.async.commit_group;"); }
__device__ __forceinline__ void cp_wait2(){ asm volatile("cp.async.wait_group 2;"); }
__device__ __forceinline__ void cp_wait1(){ asm volatile("cp.async.wait_group 1;"); }
__device__ __forceinline__ void cp_wait0(){ asm volatile("cp.async.wait_group 0;"); }

// per-CTA partials: [bh*4 + q4]
__device__ float g_Mp[512 * 4096];
__device__ float g_Sp[512 * 64];

__device__ __forceinline__ float get_cT(const float* __restrict__ delta){
    float d = delta[0];
    float t = (d > 20.f) ? d : log1pf(expf(d));
    return 1.44269504088896f / t;
}

#define MMA_TF32(C, a0,a1,a2,a3, b0,b1) \
    asm("mma.sync.aligned.m16n8k8.row.col.f32.tf32.tf32.f32 " \
        "{%0,%1,%2,%3},{%4,%5,%6,%7},{%8,%9},{%0,%1,%2,%3};" \
        : "+f"((C)[0]),"+f"((C)[1]),"+f"((C)[2]),"+f"((C)[3]) \
        : "r"(a0),"r"(a1),"r"(a2),"r"(a3), "r"(b0),"r"(b1))

// =====================================================================
// kv_mma v3: 32-row tiles, 3-stage cp.async pipeline (2 loads in
// flight). grid 512, block 128, dynamic smem 55296 B (4 CTAs/SM).
// Layout: k f[3][2304] @0 | v f[3][2304] @6912.
// =====================================================================
#define KV_SMEM (13824 * 4)

__global__ __launch_bounds__(128, 4) void kv_mma(
    const float* __restrict__ Kp, const float* __restrict__ Vp,
    const float* __restrict__ delta)
{
    extern __shared__ float pool[];

    const int bx   = blockIdx.x;
    const int bh   = bx >> 2;
    const int b    = bh >> 4, h = bh & 15;
    const int tid  = threadIdx.x;
    const int w    = tid >> 5, lane = tid & 31;
    const int g    = lane >> 2, tig = lane & 3;

    const float cT = get_cT(delta);
    const long cbase = ((long)b * 4096L) * 1024L + h * 64L;
    const float* kglob = Kp + cbase;
    const float* vglob = Vp + cbase;
    const long Lbase = (long)(bx & 3) * 1024;

    const u32 sb = (u32)__cvta_generic_to_shared(pool);

    // ones column at e=64 (cols 65-71 zero) in all three v buffers
    for (int idx = tid; idx < 768; idx += 128){
        int bf3 = idx >> 8, rem = idx & 255;
        int row = rem >> 3, col = 64 + (rem & 7);
        pool[6912 + bf3 * 2304 + row * 72 + col] = (col == 64) ? 1.f : 0.f;
    }
    __syncthreads();

    float C[4][3][4];
    #pragma unroll
    for (int mt = 0; mt < 4; mt++)
        #pragma unroll
        for (int nt = 0; nt < 3; nt++)
            #pragma unroll
            for (int i = 0; i < 4; i++) C[mt][nt][i] = 0.f;
    const int nts = (w == 3) ? 3 : 2;
    const int e0  = w * 16;

    auto load_tile = [&](int t, int bf3){
        const long l0 = Lbase + (long)t * 32;
        const float* src = (w < 2) ? kglob : vglob;
        const u32 dbase = sb + ((w < 2 ? 0 : 6912) + bf3 * 2304) * 4;
        const int rbase = (w & 1) * 16;
        #pragma unroll
        for (int i = 0; i < 8; i++){
            int slot = lane + 32 * i;
            int r = rbase + (slot >> 4);
            int ch = slot & 15;
            cpa16(dbase + (u32)(r * 72 + ch * 4) * 4, src + (l0 + r) * 1024 + ch * 4);
        }
        cp_commit();
    };

    load_tile(0, 0);
    load_tile(1, 1);

    for (int t = 0; t < 32; t++){
        __syncthreads();                 // all warps consumed tile t-1 (buffer (t+2)%3)
        if (t + 2 < 32){ load_tile(t + 2, (t + 2) % 3); cp_wait2(); }
        else if (t + 1 < 32) cp_wait1();
        else cp_wait0();
        __syncthreads();                 // tile t resident for all warps

        float* kbuf = pool + (t % 3) * 2304;
        const float* vbuf = pool + 6912 + (t % 3) * 2304;

        // ---- Phase B: 4 threads/row over 32 rows; softmax -> tf32 in place ----
        {
            const int row = tid >> 2, sub = tid & 3;
            float* rowp = kbuf + row * 72 + sub * 16;
            float4 fa = *(float4*)rowp;
            float4 fb = *(float4*)(rowp + 4);
            float4 fc = *(float4*)(rowp + 8);
            float4 fd = *(float4*)(rowp + 12);
            float v0 = ex2(cT * ((fa.x < 0.f) ? -20.f : fa.x));
            float v1 = ex2(cT * ((fa.y < 0.f) ? -20.f : fa.y));
            float v2 = ex2(cT * ((fa.z < 0.f) ? -20.f : fa.z));
            float v3 = ex2(cT * ((fa.w < 0.f) ? -20.f : fa.w));
            float v4 = ex2(cT * ((fb.x < 0.f) ? -20.f : fb.x));
            float v5 = ex2(cT * ((fb.y < 0.f) ? -20.f : fb.y));
            float v6 = ex2(cT * ((fb.z < 0.f) ? -20.f : fb.z));
            float v7 = ex2(cT * ((fb.w < 0.f) ? -20.f : fb.w));
            float v8 = ex2(cT * ((fc.x < 0.f) ? -20.f : fc.x));
            float v9 = ex2(cT * ((fc.y < 0.f) ? -20.f : fc.y));
            float vA = ex2(cT * ((fc.z < 0.f) ? -20.f : fc.z));
            float vB = ex2(cT * ((fc.w < 0.f) ? -20.f : fc.w));
            float vC = ex2(cT * ((fd.x < 0.f) ? -20.f : fd.x));
            float vD = ex2(cT * ((fd.y < 0.f) ? -20.f : fd.y));
            float vE = ex2(cT * ((fd.z < 0.f) ? -20.f : fd.z));
            float vF = ex2(cT * ((fd.w < 0.f) ? -20.f : fd.w));
            float sm = (((v0 + v1) + (v2 + v3)) + ((v4 + v5) + (v6 + v7)))
                     + (((v8 + v9) + (vA + vB)) + ((vC + vD) + (vE + vF)));
            sm += __shfl_xor_sync(FULL, sm, 1);
            sm += __shfl_xor_sync(FULL, sm, 2);
            float rs = frcp(sm);
            uint4 oa, ob, oc, od;
            oa.x = totf32(v0 * rs); oa.y = totf32(v1 * rs);
            oa.z = totf32(v2 * rs); oa.w = totf32(v3 * rs);
            ob.x = totf32(v4 * rs); ob.y = totf32(v5 * rs);
            ob.z = totf32(v6 * rs); ob.w = totf32(v7 * rs);
            oc.x = totf32(v8 * rs); oc.y = totf32(v9 * rs);
            oc.z = totf32(vA * rs); oc.w = totf32(vB * rs);
            od.x = totf32(vC * rs); od.y = totf32(vD * rs);
            od.z = totf32(vE * rs); od.w = totf32(vF * rs);
            *(uint4*)rowp        = oa;
            *(uint4*)(rowp + 4)  = ob;
            *(uint4*)(rowp + 8)  = oc;
            *(uint4*)(rowp + 12) = od;
        }
        __syncthreads();                 // converted tile ready

        // ---- Phase C: 4 k-tiles of 8 rows; MMA ----
        {
            const u32* kB = (const u32*)kbuf;
            u32 bf[4][3][2];
            #pragma unroll
            for (int kt = 0; kt < 4; kt++)
                #pragma unroll
                for (int nt = 0; nt < 3; nt++)
                    if (nt < nts){
                        float b0 = vbuf[(kt * 8 + tig) * 72 + e0 + nt * 8 + g];
                        float b1 = vbuf[(kt * 8 + tig + 4) * 72 + e0 + nt * 8 + g];
                        bf[kt][nt][0] = totf32(b0);
                        bf[kt][nt][1] = totf32(b1);
                    }
            #pragma unroll
            for (int mt = 0; mt < 4; mt++){
                #pragma unroll
                for (int kt = 0; kt < 4; kt++){
                    u32 a0 = kB[(kt * 8 + tig) * 72 + mt * 16 + g];
                    u32 a1 = kB[(kt * 8 + tig) * 72 + mt * 16 + g + 8];
                    u32 a2 = kB[(kt * 8 + tig + 4) * 72 + mt * 16 + g];
                    u32 a3 = kB[(kt * 8 + tig + 4) * 72 + mt * 16 + g + 8];
                    #pragma unroll
                    for (int nt = 0; nt < 3; nt++)
                        if (nt < nts) MMA_TF32(C[mt][nt], a0, a1, a2, a3,
                                               bf[kt][nt][0], bf[kt][nt][1]);
                }
            }
        }
    }

    float* Mp = g_Mp + (long)bx * 4096;
    #pragma unroll
    for (int mt = 0; mt < 4; mt++){
        #pragma unroll
        for (int nt = 0; nt < 3; nt++){
            if (nt >= nts) continue;
            if (w == 3 && nt == 2){
                if (tig == 0){
                    g_Sp[bx * 64 + mt * 16 + g]     = C[mt][2][0];
                    g_Sp[bx * 64 + mt * 16 + g + 8] = C[mt][2][2];
                }
            } else {
                const int e = e0 + nt * 8 + 2 * tig;
                *(float2*)(Mp + (mt * 16 + g) * 64 + e)
                    = make_float2(C[mt][nt][0], C[mt][nt][1]);
                *(float2*)(Mp + (mt * 16 + g + 8) * 64 + e)
                    = make_float2(C[mt][nt][2], C[mt][nt][3]);
            }
        }
    }
}

// =====================================================================
// out_mma v6: independent warps + 3-stage per-warp pipeline (2 loads
// in flight). grid 1024 (8 CTAs/bh), block 128, 2 CTAs/SM.
// Dynamic smem: sM f[64*68] | wbuf f[4][3][16][68] | sSh f[64].
// =====================================================================
#define SM_BYTES    17408
#define WBUF_BYTES  52224
#define OUT_SMEM    (SM_BYTES + WBUF_BYTES + 256)

__global__ __launch_bounds__(128, 2) void out_mma(
    const float* __restrict__ Qp, float* __restrict__ Out,
    const float* __restrict__ delta)
{
    extern __shared__ char osm[];
    float* sM   = (float*)osm;                         // [64*68], init only
    float* wall = (float*)(osm + SM_BYTES);            // [4][3][1088]
    float* sSh  = (float*)(osm + SM_BYTES + WBUF_BYTES);

    const int bx   = blockIdx.x;
    const int bh   = bx >> 3;
    const int b    = bh >> 4, h = bh & 15;
    const int tid  = threadIdx.x;
    const int w    = tid >> 5, lane = tid & 31;
    const int g    = lane >> 2, tig = lane & 3;

    const float cT = get_cT(delta);
    const long cbase = ((long)b * 4096L) * 1024L + h * 64L;
    const long Lbase = (long)(bx & 7) * 512;

    float* wbuf = wall + w * 3264;                     // this warp's 3 buffers
    const u32 wb = (u32)__cvta_generic_to_shared(wbuf);

    auto load_tile = [&](int t, int buf){
        const long l0 = Lbase + (long)t * 64 + 16 * w;
        const u32 dbase = wb + (u32)(buf * 1088) * 4;
        #pragma unroll
        for (int i = 0; i < 8; i++){
            int slot = lane + 32 * i;          // 0..255
            int r = slot >> 4, ch = slot & 15;
            cpa16(dbase + (u32)(r * 68 + ch * 4) * 4, Qp + cbase + (l0 + r) * 1024 + ch * 4);
        }
        cp_commit();
    };

    load_tile(0, 0);   // prefetch overlaps M init (disjoint smem regions)
    load_tile(1, 1);

    if (tid < 64){
        float s = 0.f;
        #pragma unroll
        for (int p = 0; p < 4; p++) s += g_Sp[(bh * 4 + p) * 64 + tid];
        sSh[tid] = s;
    }
    for (int i = tid; i < 1024; i += 128){
        const int d = i >> 4, c4 = (i & 15) * 4;
        float4 a = make_float4(0.f, 0.f, 0.f, 0.f);
        #pragma unroll
        for (int p = 0; p < 4; p++){
            float4 v = *(const float4*)(g_Mp + (long)(bh * 4 + p) * 4096 + d * 64 + c4);
            a.x += v.x; a.y += v.y; a.z += v.z; a.w += v.w;
        }
        *(float4*)(sM + d * 68 + c4) = a;
    }
    __syncthreads();   // sM/sSh ready (region never recycled — last block barrier)

    u32 BF[8][8][2];
    #pragma unroll
    for (int kt = 0; kt < 8; kt++)
        #pragma unroll
        for (int nt = 0; nt < 8; nt++){
            BF[kt][nt][0] = totf32(sM[(kt * 8 + tig)     * 68 + nt * 8 + g]);
            BF[kt][nt][1] = totf32(sM[(kt * 8 + tig + 4) * 68 + nt * 8 + g]);
        }
    float s_reg[16];
    #pragma unroll
    for (int j = 0; j < 16; j++) s_reg[j] = sSh[tig + 4 * j];

    for (int t = 0; t < 8; t++){
        if (t + 2 < 8){ load_tile(t + 2, (t + 2) % 3); cp_wait2(); }
        else if (t + 1 < 8) cp_wait1();
        else cp_wait0();
        __syncwarp();

        const float* r0p = wbuf + (t % 3) * 1088 + g * 68;
        const float* r1p = r0p + 8 * 68;

        float C[8][4];
        #pragma unroll
        for (int nt = 0; nt < 8; nt++)
            #pragma unroll
            for (int i = 0; i < 4; i++) C[nt][i] = 0.f;

        float sm0 = 0.f, u0 = 0.f, sm1 = 0.f, u1 = 0.f;

        #pragma unroll
        for (int kt = 0; kt < 8; kt++){
            float x0 = r0p[kt * 8 + tig];
            float x1 = r1p[kt * 8 + tig];
            float x2 = r0p[kt * 8 + tig + 4];
            float x3 = r1p[kt * 8 + tig + 4];
            float e0v = ex2(cT * ((x0 < 0.f) ? -20.f : x0));
            float e1v = ex2(cT * ((x1 < 0.f) ? -20.f : x1));
            float e2v = ex2(cT * ((x2 < 0.f) ? -20.f : x2));
            float e3v = ex2(cT * ((x3 < 0.f) ? -20.f : x3));
            sm0 += e0v + e2v;
            sm1 += e1v + e3v;
            u0 = fmaf(e0v, s_reg[2 * kt], fmaf(e2v, s_reg[2 * kt + 1], u0));
            u1 = fmaf(e1v, s_reg[2 * kt], fmaf(e3v, s_reg[2 * kt + 1], u1));
            u32 a0 = totf32(e0v), a1 = totf32(e1v);
            u32 a2 = totf32(e2v), a3 = totf32(e3v);
            #pragma unroll
            for (int nt = 0; nt < 8; nt++)
                MMA_TF32(C[nt], a0, a1, a2, a3, BF[kt][nt][0], BF[kt][nt][1]);
        }

        #pragma unroll
        for (int o = 1; o <= 2; o <<= 1){
            sm0 += __shfl_xor_sync(FULL, sm0, o);
            u0  += __shfl_xor_sync(FULL, u0,  o);
            sm1 += __shfl_xor_sync(FULL, sm1, o);
            u1  += __shfl_xor_sync(FULL, u1,  o);
        }
        const float gv0 = frcp(u0 + 1e-6f * sm0);
        const float gv1 = frcp(u1 + 1e-6f * sm1);

        const long l0 = Lbase + (long)t * 64 + 16 * w;
        float* o0 = Out + cbase + (l0 + g) * 1024 + 2 * tig;
        float* o1 = Out + cbase + (l0 + g + 8) * 1024 + 2 * tig;
        #pragma unroll
        for (int nt = 0; nt < 8; nt++){
            *(float2*)(o0 + nt * 8) = make_float2(C[nt][0] * gv0, C[nt][1] * gv0);
            *(float2*)(o1 + nt * 8) = make_float2(C[nt][2] * gv1, C[nt][3] * gv1);
        }
        __syncwarp();
    }
}

extern "C" void kernel_launch(void* const* d_in, const int* in_sizes, int n_in,
                              void* d_out, int out_size)
{
    const float* Q     = (const float*)d_in[0];
    const float* K     = (const float*)d_in[1];
    const float* V     = (const float*)d_in[2];
    const float* delta = (const float*)d_in[3];
    float* Out = (float*)d_out;

    cudaFuncSetAttribute(kv_mma, cudaFuncAttributeMaxDynamicSharedMemorySize, KV_SMEM / 4 * 4);
    kv_mma<<<512, 128, 13824 * 4>>>(K, V, delta);
    cudaFuncSetAttribute(out_mma, cudaFuncAttributeMaxDynamicSharedMemorySize, OUT_SMEM);
    out_mma<<<1024, 128, OUT_SMEM>>>(Q, Out, delta);
}